// round 14
// baseline (speedup 1.0000x reference)
#include <cuda_runtime.h>
#include <cuda_fp16.h>
#include <cstdint>

// ============================================================
// Flash attention B=16 S=4096 D=64, fp32 in/out, HMMA path.
// Round 14: round-13 main loop (fp16x2 exp2 softmax, ones-MMA
// row sums, split-K=2, 4-stage pipeline). Changes:
//  - combine kernel FUSED into main kernel: after a fenced
//    partial write, per-job atomicAdd picks the later CTA,
//    which combines (own regs + peer partial), normalizes,
//    writes O, and resets the flag for graph replay.
//  - prep: 4 float4/thread for memory-level parallelism.
// ============================================================

#define BATCH 16
#define SEQ   4096
#define HD    64
#define BQ    128
#define BK    64
#define KSPLIT 2
#define SHALF (SEQ / KSPLIT)   // 2048
#define NTH   (SHALF / BK)     // 32 tiles per half-job
#define THREADS 128
#define NJOBS (BATCH * (SEQ / BQ))     // 512
#define QSCALE 0.18033688011112042f   // log2(e)/sqrt(64)
#define ONES2  0x3C003C00u             // __half2(1,1)

__device__ __half g_Qh[BATCH * SEQ * HD];
__device__ __half g_Kh[BATCH * SEQ * HD];
__device__ __half g_Vh[BATCH * SEQ * HD];
__device__ float  g_Po[KSPLIT * BATCH * SEQ * HD];   // unnormalized O halves
__device__ float  g_Pl[KSPLIT * BATCH * SEQ];        // row sums l halves
__device__ int    g_flag[NJOBS];                      // zero-init; reset each replay

static __device__ __forceinline__ uint32_t smem_u32(const void* p) {
    uint32_t a;
    asm("{ .reg .u64 t; cvta.to.shared.u64 t, %1; cvt.u32.u64 %0, t; }"
        : "=r"(a) : "l"(p));
    return a;
}
static __device__ __forceinline__ void ldm_x4(uint32_t r[4], uint32_t addr) {
    asm volatile("ldmatrix.sync.aligned.m8n8.x4.shared.b16 {%0,%1,%2,%3}, [%4];"
                 : "=r"(r[0]), "=r"(r[1]), "=r"(r[2]), "=r"(r[3])
                 : "r"(addr) : "memory");
}
static __device__ __forceinline__ void ldm_x4_t(uint32_t r[4], uint32_t addr) {
    asm volatile("ldmatrix.sync.aligned.m8n8.x4.trans.shared.b16 {%0,%1,%2,%3}, [%4];"
                 : "=r"(r[0]), "=r"(r[1]), "=r"(r[2]), "=r"(r[3])
                 : "r"(addr) : "memory");
}
static __device__ __forceinline__ void mma16816(float (&c)[4], const uint32_t (&a)[4],
                                                uint32_t b0, uint32_t b1) {
    asm volatile("mma.sync.aligned.m16n8k16.row.col.f32.f16.f16.f32 "
                 "{%0,%1,%2,%3}, {%4,%5,%6,%7}, {%8,%9}, {%0,%1,%2,%3};"
                 : "+f"(c[0]), "+f"(c[1]), "+f"(c[2]), "+f"(c[3])
                 : "r"(a[0]), "r"(a[1]), "r"(a[2]), "r"(a[3]), "r"(b0), "r"(b1));
}
static __device__ __forceinline__ void cpa16(uint32_t dst, const void* src) {
    asm volatile("cp.async.cg.shared.global [%0], [%1], 16;"
                 :: "r"(dst), "l"(src) : "memory");
}
#define CPA_COMMIT() asm volatile("cp.async.commit_group;" ::: "memory")
#define CPA_WAIT0()  asm volatile("cp.async.wait_group 0;" ::: "memory")

static __device__ __forceinline__ uint32_t h2u(__half2 h) {
    return *reinterpret_cast<uint32_t*>(&h);
}
static __device__ __forceinline__ uint32_t swz(uint32_t off) {
    return off ^ ((off >> 3) & 0x70);
}
// pack two fp32 scores -> fp16x2, exp2 both halves in one MUFU op (no shift)
static __device__ __forceinline__ uint32_t p16x2(float a, float b) {
    __half2 h = __floats2half2_rn(a, b);
    uint32_t r;
    asm("ex2.approx.f16x2 %0, %1;" : "=r"(r) : "r"(h2u(h)));
    return r;
}

// ---------------- prep: fp32 -> fp16 scratch (4 float4 / thread) ----------------
__global__ __launch_bounds__(256)
void prep(const float4* __restrict__ Q4, const float4* __restrict__ K4,
          const float4* __restrict__ V4)
{
    int base = blockIdx.x * 1024 + threadIdx.x;
    #pragma unroll
    for (int u = 0; u < 4; u++) {
        int i = base + u * 256;
        float4 q = Q4[i], k = K4[i], v = V4[i];
        reinterpret_cast<uint2*>(g_Qh)[i] = make_uint2(
            h2u(__floats2half2_rn(q.x * QSCALE, q.y * QSCALE)),
            h2u(__floats2half2_rn(q.z * QSCALE, q.w * QSCALE)));
        reinterpret_cast<uint2*>(g_Kh)[i] = make_uint2(
            h2u(__floats2half2_rn(k.x, k.y)), h2u(__floats2half2_rn(k.z, k.w)));
        reinterpret_cast<uint2*>(g_Vh)[i] = make_uint2(
            h2u(__floats2half2_rn(v.x, v.y)), h2u(__floats2half2_rn(v.z, v.w)));
    }
}

// ---------------- main attention kernel (one K-half) ----------------
// smem: 4 x 16KB stages; in each: K tile +0 (8KB), V tile +8192 (8KB).
__global__ __launch_bounds__(THREADS, 3)
void attn_hmma12(float* __restrict__ O)
{
    __shared__ __align__(1024) char sm[65536];
    __shared__ int s_pos;
    const uint32_t smb = smem_u32(sm);
    const int tid  = threadIdx.x;
    const int lane = tid & 31;
    const int w    = tid >> 5;            // 0..3, warp owns 32 query rows
    const int b    = blockIdx.y;
    const int q0   = blockIdx.x * BQ;
    const int z    = blockIdx.z;          // K half
    const int job  = b * (SEQ / BQ) + blockIdx.x;

    const __half* Qh_s = g_Qh + ((size_t)b * SEQ + q0) * HD;
    const __half* Kb   = g_Kh + ((size_t)b * SEQ + (size_t)z * SHALF) * HD;
    const __half* Vb   = g_Vh + ((size_t)b * SEQ + (size_t)z * SHALF) * HD;

    // ---- stage Q (16KB, stage 0 area) into smem, ldmatrix to regs ----
    #pragma unroll
    for (int j = 0; j < 8; j++) {
        int idx = tid + j * THREADS;                 // 0..1023
        uint32_t off = swz((uint32_t)(idx >> 3) * 128 + (uint32_t)(idx & 7) * 16);
        cpa16(smb + off, Qh_s + idx * 8);
    }
    CPA_COMMIT(); CPA_WAIT0();
    __syncthreads();

    uint32_t q[2][4][4];
    {
        uint32_t colb = (uint32_t)(lane >> 4) * 16;
        #pragma unroll
        for (int rt = 0; rt < 2; rt++) {
            uint32_t row = (uint32_t)w * 32 + (uint32_t)rt * 16 + (lane & 15);
            #pragma unroll
            for (int c = 0; c < 4; c++) {
                uint32_t off = swz(row * 128 + (uint32_t)c * 32 + colb);
                ldm_x4(q[rt][c], smb + off);
            }
        }
    }
    __syncthreads();   // Q staging now reusable as stage 0

    // ---- tile loader ----
    auto load_tile = [&](int t) {
        uint32_t nb = smb + (uint32_t)(t & 3) * 16384u;
        const __half* kn = Kb + (size_t)t * BK * HD;
        const __half* vn = Vb + (size_t)t * BK * HD;
        #pragma unroll
        for (int j = 0; j < 4; j++) {
            int idx = tid + j * THREADS;             // 0..511
            uint32_t off = swz((uint32_t)(idx >> 3) * 128 + (uint32_t)(idx & 7) * 16);
            cpa16(nb + off,        kn + idx * 8);
            cpa16(nb + 8192 + off, vn + idx * 8);
        }
    };

    load_tile(0); CPA_COMMIT();
    load_tile(1); CPA_COMMIT();
    CPA_WAIT0();
    __syncthreads();

    float o[2][8][4];
    #pragma unroll
    for (int rt = 0; rt < 2; rt++)
        #pragma unroll
        for (int j = 0; j < 8; j++)
            o[rt][j][0] = o[rt][j][1] = o[rt][j][2] = o[rt][j][3] = 0.f;
    float ol[2][4];
    ol[0][0] = ol[0][1] = ol[0][2] = ol[0][3] = 0.f;
    ol[1][0] = ol[1][1] = ol[1][2] = ol[1][3] = 0.f;

    const uint32_t krow  = (uint32_t)(lane & 15);
    const uint32_t kcolb = (uint32_t)(lane >> 4) * 16;

    auto do_tile = [&](int t) {
        const uint32_t base = smb + (uint32_t)(t & 3) * 16384u;
        #pragma unroll
        for (int h = 0; h < 2; h++) {
            float s[2][4][4];
            #pragma unroll
            for (int rt = 0; rt < 2; rt++)
                #pragma unroll
                for (int j = 0; j < 4; j++)
                    s[rt][j][0] = s[rt][j][1] = s[rt][j][2] = s[rt][j][3] = 0.f;

            #pragma unroll
            for (int g = 0; g < 2; g++) {
                uint32_t kg = (uint32_t)(h * 2 + g);
                #pragma unroll
                for (int c = 0; c < 4; c++) {
                    uint32_t off = swz((kg * 16 + krow) * 128 + (uint32_t)c * 32 + kcolb);
                    uint32_t kb[4];
                    ldm_x4(kb, base + off);
                    #pragma unroll
                    for (int rt = 0; rt < 2; rt++) {
                        mma16816(s[rt][2 * g],     q[rt][c], kb[0], kb[2]);
                        mma16816(s[rt][2 * g + 1], q[rt][c], kb[1], kb[3]);
                    }
                }
            }

            uint32_t pu[2][4][2];
            #pragma unroll
            for (int rt = 0; rt < 2; rt++)
                #pragma unroll
                for (int j = 0; j < 4; j++) {
                    pu[rt][j][0] = p16x2(s[rt][j][0], s[rt][j][1]);
                    pu[rt][j][1] = p16x2(s[rt][j][2], s[rt][j][3]);
                }

            #pragma unroll
            for (int kk = 0; kk < 2; kk++) {
                uint32_t kg = (uint32_t)(h * 2 + kk);
                uint32_t a0[4] = { pu[0][2 * kk][0], pu[0][2 * kk][1],
                                   pu[0][2 * kk + 1][0], pu[0][2 * kk + 1][1] };
                uint32_t a1[4] = { pu[1][2 * kk][0], pu[1][2 * kk][1],
                                   pu[1][2 * kk + 1][0], pu[1][2 * kk + 1][1] };
                mma16816(ol[0], a0, ONES2, ONES2);
                mma16816(ol[1], a1, ONES2, ONES2);
                #pragma unroll
                for (int nn = 0; nn < 4; nn++) {
                    uint32_t off = swz((kg * 16 + krow) * 128 + (uint32_t)nn * 32 + kcolb);
                    uint32_t vb[4];
                    ldm_x4_t(vb, base + 8192 + off);
                    mma16816(o[0][2 * nn],     a0, vb[0], vb[1]);
                    mma16816(o[0][2 * nn + 1], a0, vb[2], vb[3]);
                    mma16816(o[1][2 * nn],     a1, vb[0], vb[1]);
                    mma16816(o[1][2 * nn + 1], a1, vb[2], vb[3]);
                }
            }
        }
    };

    for (int t = 0; t < NTH; t += 2) {
        if (t + 2 < NTH) { load_tile(t + 2); }
        CPA_COMMIT();
        do_tile(t);
        if (t + 3 < NTH) { load_tile(t + 3); }
        CPA_COMMIT();
        do_tile(t + 1);
        CPA_WAIT0();
        __syncthreads();
    }

    // ---- write own partial (unnormalized o + row sums l) ----
    float* Po = g_Po + ((size_t)z * BATCH + b) * SEQ * HD;
    float* Pl = g_Pl + ((size_t)z * BATCH + b) * SEQ;
    #pragma unroll
    for (int rt = 0; rt < 2; rt++) {
        const int r0 = q0 + w * 32 + rt * 16 + (lane >> 2);
        const int r1 = r0 + 8;
        if ((lane & 3) == 0) {
            Pl[r0] = ol[rt][0];
            Pl[r1] = ol[rt][2];
        }
        #pragma unroll
        for (int j = 0; j < 8; j++) {
            int col = j * 8 + (lane & 3) * 2;
            *reinterpret_cast<float2*>(Po + (size_t)r0 * HD + col) =
                make_float2(o[rt][j][0], o[rt][j][1]);
            *reinterpret_cast<float2*>(Po + (size_t)r1 * HD + col) =
                make_float2(o[rt][j][2], o[rt][j][3]);
        }
    }

    // ---- fused combine: later CTA of the job merges and writes O ----
    __threadfence();                       // partial visible before the add
    __syncthreads();                       // all threads' writes included
    if (tid == 0) s_pos = atomicAdd(&g_flag[job], 1);
    __syncthreads();
    if (s_pos == 0) return;                // earlier CTA: done

    __threadfence();                       // acquire: peer's fenced writes visible
    const int zo = 1 - z;
    const float* Qo = g_Po + ((size_t)zo * BATCH + b) * SEQ * HD;
    const float* Lo = g_Pl + ((size_t)zo * BATCH + b) * SEQ;
    float* Ob = O + (size_t)b * SEQ * HD;
    #pragma unroll
    for (int rt = 0; rt < 2; rt++) {
        const int r0 = q0 + w * 32 + rt * 16 + (lane >> 2);
        const int r1 = r0 + 8;
        const float inv0 = 1.0f / (ol[rt][0] + Lo[r0]);
        const float inv1 = 1.0f / (ol[rt][2] + Lo[r1]);
        #pragma unroll
        for (int j = 0; j < 8; j++) {
            int col = j * 8 + (lane & 3) * 2;
            float2 e0 = *reinterpret_cast<const float2*>(Qo + (size_t)r0 * HD + col);
            float2 e1 = *reinterpret_cast<const float2*>(Qo + (size_t)r1 * HD + col);
            *reinterpret_cast<float2*>(Ob + (size_t)r0 * HD + col) =
                make_float2((o[rt][j][0] + e0.x) * inv0, (o[rt][j][1] + e0.y) * inv0);
            *reinterpret_cast<float2*>(Ob + (size_t)r1 * HD + col) =
                make_float2((o[rt][j][2] + e1.x) * inv1, (o[rt][j][3] + e1.y) * inv1);
        }
    }
    if (tid == 0) g_flag[job] = 0;         // reset for next graph replay
}

extern "C" void kernel_launch(void* const* d_in, const int* in_sizes, int n_in,
                              void* d_out, int out_size)
{
    (void)in_sizes; (void)n_in; (void)out_size;
    const float* Q = (const float*)d_in[0];
    const float* K = (const float*)d_in[1];
    const float* V = (const float*)d_in[2];
    float* O = (float*)d_out;

    prep<<<1024, 256>>>((const float4*)Q, (const float4*)K, (const float4*)V);

    dim3 grid(SEQ / BQ, BATCH, KSPLIT);   // (32, 16, 2) = 1024 half-jobs
    attn_hmma12<<<grid, THREADS>>>(O);
}

// round 15
// speedup vs baseline: 1.0234x; 1.0234x over previous
#include <cuda_runtime.h>
#include <cuda_fp16.h>
#include <cstdint>

// ============================================================
// Flash attention B=16 S=4096 D=64, fp32 in/out, HMMA path.
// Round 15: round-14 fused split-K, but wait-free role split:
// first finisher writes partial + ready-flag; LATER finisher
// never writes a partial (keeps o,l in regs), spins briefly on
// ready, combines peer partial + registers, writes O, resets
// flags for graph replay. Saves 16MB partial traffic + tail.
// ============================================================

#define BATCH 16
#define SEQ   4096
#define HD    64
#define BQ    128
#define BK    64
#define KSPLIT 2
#define SHALF (SEQ / KSPLIT)   // 2048
#define NTH   (SHALF / BK)     // 32 tiles per half-job
#define THREADS 128
#define NJOBS (BATCH * (SEQ / BQ))     // 512
#define QSCALE 0.18033688011112042f   // log2(e)/sqrt(64)
#define ONES2  0x3C003C00u             // __half2(1,1)

__device__ __half g_Qh[BATCH * SEQ * HD];
__device__ __half g_Kh[BATCH * SEQ * HD];
__device__ __half g_Vh[BATCH * SEQ * HD];
__device__ float  g_Po[NJOBS * BQ * HD];   // one partial per job (first finisher)
__device__ float  g_Pl[NJOBS * BQ];        // row sums of that partial
__device__ int    g_flag[NJOBS];           // arrival counter (zero-init)
__device__ int    g_ready[NJOBS];          // partial-visible flag (zero-init)

static __device__ __forceinline__ uint32_t smem_u32(const void* p) {
    uint32_t a;
    asm("{ .reg .u64 t; cvta.to.shared.u64 t, %1; cvt.u32.u64 %0, t; }"
        : "=r"(a) : "l"(p));
    return a;
}
static __device__ __forceinline__ void ldm_x4(uint32_t r[4], uint32_t addr) {
    asm volatile("ldmatrix.sync.aligned.m8n8.x4.shared.b16 {%0,%1,%2,%3}, [%4];"
                 : "=r"(r[0]), "=r"(r[1]), "=r"(r[2]), "=r"(r[3])
                 : "r"(addr) : "memory");
}
static __device__ __forceinline__ void ldm_x4_t(uint32_t r[4], uint32_t addr) {
    asm volatile("ldmatrix.sync.aligned.m8n8.x4.trans.shared.b16 {%0,%1,%2,%3}, [%4];"
                 : "=r"(r[0]), "=r"(r[1]), "=r"(r[2]), "=r"(r[3])
                 : "r"(addr) : "memory");
}
static __device__ __forceinline__ void mma16816(float (&c)[4], const uint32_t (&a)[4],
                                                uint32_t b0, uint32_t b1) {
    asm volatile("mma.sync.aligned.m16n8k16.row.col.f32.f16.f16.f32 "
                 "{%0,%1,%2,%3}, {%4,%5,%6,%7}, {%8,%9}, {%0,%1,%2,%3};"
                 : "+f"(c[0]), "+f"(c[1]), "+f"(c[2]), "+f"(c[3])
                 : "r"(a[0]), "r"(a[1]), "r"(a[2]), "r"(a[3]), "r"(b0), "r"(b1));
}
static __device__ __forceinline__ void cpa16(uint32_t dst, const void* src) {
    asm volatile("cp.async.cg.shared.global [%0], [%1], 16;"
                 :: "r"(dst), "l"(src) : "memory");
}
#define CPA_COMMIT() asm volatile("cp.async.commit_group;" ::: "memory")
#define CPA_WAIT0()  asm volatile("cp.async.wait_group 0;" ::: "memory")

static __device__ __forceinline__ uint32_t h2u(__half2 h) {
    return *reinterpret_cast<uint32_t*>(&h);
}
static __device__ __forceinline__ uint32_t swz(uint32_t off) {
    return off ^ ((off >> 3) & 0x70);
}
// pack two fp32 scores -> fp16x2, exp2 both halves in one MUFU op (no shift)
static __device__ __forceinline__ uint32_t p16x2(float a, float b) {
    __half2 h = __floats2half2_rn(a, b);
    uint32_t r;
    asm("ex2.approx.f16x2 %0, %1;" : "=r"(r) : "r"(h2u(h)));
    return r;
}

// ---------------- prep: fp32 -> fp16 scratch (2 float4 / thread) ----------------
__global__ __launch_bounds__(256)
void prep(const float4* __restrict__ Q4, const float4* __restrict__ K4,
          const float4* __restrict__ V4)
{
    int i0 = blockIdx.x * 512 + threadIdx.x;
    int i1 = i0 + 256;
    float4 qa = Q4[i0], qb = Q4[i1];
    float4 ka = K4[i0], kb = K4[i1];
    float4 va = V4[i0], vb = V4[i1];
    reinterpret_cast<uint2*>(g_Qh)[i0] = make_uint2(
        h2u(__floats2half2_rn(qa.x * QSCALE, qa.y * QSCALE)),
        h2u(__floats2half2_rn(qa.z * QSCALE, qa.w * QSCALE)));
    reinterpret_cast<uint2*>(g_Qh)[i1] = make_uint2(
        h2u(__floats2half2_rn(qb.x * QSCALE, qb.y * QSCALE)),
        h2u(__floats2half2_rn(qb.z * QSCALE, qb.w * QSCALE)));
    reinterpret_cast<uint2*>(g_Kh)[i0] = make_uint2(
        h2u(__floats2half2_rn(ka.x, ka.y)), h2u(__floats2half2_rn(ka.z, ka.w)));
    reinterpret_cast<uint2*>(g_Kh)[i1] = make_uint2(
        h2u(__floats2half2_rn(kb.x, kb.y)), h2u(__floats2half2_rn(kb.z, kb.w)));
    reinterpret_cast<uint2*>(g_Vh)[i0] = make_uint2(
        h2u(__floats2half2_rn(va.x, va.y)), h2u(__floats2half2_rn(va.z, va.w)));
    reinterpret_cast<uint2*>(g_Vh)[i1] = make_uint2(
        h2u(__floats2half2_rn(vb.x, vb.y)), h2u(__floats2half2_rn(vb.z, vb.w)));
}

// ---------------- main attention kernel (one K-half) ----------------
// smem: 4 x 16KB stages; in each: K tile +0 (8KB), V tile +8192 (8KB).
__global__ __launch_bounds__(THREADS, 3)
void attn_hmma13(float* __restrict__ O)
{
    __shared__ __align__(1024) char sm[65536];
    __shared__ int s_pos;
    const uint32_t smb = smem_u32(sm);
    const int tid  = threadIdx.x;
    const int lane = tid & 31;
    const int w    = tid >> 5;            // 0..3, warp owns 32 query rows
    const int b    = blockIdx.y;
    const int q0   = blockIdx.x * BQ;
    const int z    = blockIdx.z;          // K half
    const int job  = b * (SEQ / BQ) + blockIdx.x;

    const __half* Qh_s = g_Qh + ((size_t)b * SEQ + q0) * HD;
    const __half* Kb   = g_Kh + ((size_t)b * SEQ + (size_t)z * SHALF) * HD;
    const __half* Vb   = g_Vh + ((size_t)b * SEQ + (size_t)z * SHALF) * HD;

    // ---- stage Q (16KB, stage 0 area) into smem, ldmatrix to regs ----
    #pragma unroll
    for (int j = 0; j < 8; j++) {
        int idx = tid + j * THREADS;                 // 0..1023
        uint32_t off = swz((uint32_t)(idx >> 3) * 128 + (uint32_t)(idx & 7) * 16);
        cpa16(smb + off, Qh_s + idx * 8);
    }
    CPA_COMMIT(); CPA_WAIT0();
    __syncthreads();

    uint32_t q[2][4][4];
    {
        uint32_t colb = (uint32_t)(lane >> 4) * 16;
        #pragma unroll
        for (int rt = 0; rt < 2; rt++) {
            uint32_t row = (uint32_t)w * 32 + (uint32_t)rt * 16 + (lane & 15);
            #pragma unroll
            for (int c = 0; c < 4; c++) {
                uint32_t off = swz(row * 128 + (uint32_t)c * 32 + colb);
                ldm_x4(q[rt][c], smb + off);
            }
        }
    }
    __syncthreads();   // Q staging now reusable as stage 0

    auto load_tile = [&](int t) {
        uint32_t nb = smb + (uint32_t)(t & 3) * 16384u;
        const __half* kn = Kb + (size_t)t * BK * HD;
        const __half* vn = Vb + (size_t)t * BK * HD;
        #pragma unroll
        for (int j = 0; j < 4; j++) {
            int idx = tid + j * THREADS;             // 0..511
            uint32_t off = swz((uint32_t)(idx >> 3) * 128 + (uint32_t)(idx & 7) * 16);
            cpa16(nb + off,        kn + idx * 8);
            cpa16(nb + 8192 + off, vn + idx * 8);
        }
    };

    load_tile(0); CPA_COMMIT();
    load_tile(1); CPA_COMMIT();
    CPA_WAIT0();
    __syncthreads();

    float o[2][8][4];
    #pragma unroll
    for (int rt = 0; rt < 2; rt++)
        #pragma unroll
        for (int j = 0; j < 8; j++)
            o[rt][j][0] = o[rt][j][1] = o[rt][j][2] = o[rt][j][3] = 0.f;
    float ol[2][4];
    ol[0][0] = ol[0][1] = ol[0][2] = ol[0][3] = 0.f;
    ol[1][0] = ol[1][1] = ol[1][2] = ol[1][3] = 0.f;

    const uint32_t krow  = (uint32_t)(lane & 15);
    const uint32_t kcolb = (uint32_t)(lane >> 4) * 16;

    auto do_tile = [&](int t) {
        const uint32_t base = smb + (uint32_t)(t & 3) * 16384u;
        #pragma unroll
        for (int h = 0; h < 2; h++) {
            float s[2][4][4];
            #pragma unroll
            for (int rt = 0; rt < 2; rt++)
                #pragma unroll
                for (int j = 0; j < 4; j++)
                    s[rt][j][0] = s[rt][j][1] = s[rt][j][2] = s[rt][j][3] = 0.f;

            #pragma unroll
            for (int g = 0; g < 2; g++) {
                uint32_t kg = (uint32_t)(h * 2 + g);
                #pragma unroll
                for (int c = 0; c < 4; c++) {
                    uint32_t off = swz((kg * 16 + krow) * 128 + (uint32_t)c * 32 + kcolb);
                    uint32_t kb[4];
                    ldm_x4(kb, base + off);
                    #pragma unroll
                    for (int rt = 0; rt < 2; rt++) {
                        mma16816(s[rt][2 * g],     q[rt][c], kb[0], kb[2]);
                        mma16816(s[rt][2 * g + 1], q[rt][c], kb[1], kb[3]);
                    }
                }
            }

            uint32_t pu[2][4][2];
            #pragma unroll
            for (int rt = 0; rt < 2; rt++)
                #pragma unroll
                for (int j = 0; j < 4; j++) {
                    pu[rt][j][0] = p16x2(s[rt][j][0], s[rt][j][1]);
                    pu[rt][j][1] = p16x2(s[rt][j][2], s[rt][j][3]);
                }

            #pragma unroll
            for (int kk = 0; kk < 2; kk++) {
                uint32_t kg = (uint32_t)(h * 2 + kk);
                uint32_t a0[4] = { pu[0][2 * kk][0], pu[0][2 * kk][1],
                                   pu[0][2 * kk + 1][0], pu[0][2 * kk + 1][1] };
                uint32_t a1[4] = { pu[1][2 * kk][0], pu[1][2 * kk][1],
                                   pu[1][2 * kk + 1][0], pu[1][2 * kk + 1][1] };
                mma16816(ol[0], a0, ONES2, ONES2);
                mma16816(ol[1], a1, ONES2, ONES2);
                #pragma unroll
                for (int nn = 0; nn < 4; nn++) {
                    uint32_t off = swz((kg * 16 + krow) * 128 + (uint32_t)nn * 32 + kcolb);
                    uint32_t vb[4];
                    ldm_x4_t(vb, base + 8192 + off);
                    mma16816(o[0][2 * nn],     a0, vb[0], vb[1]);
                    mma16816(o[0][2 * nn + 1], a0, vb[2], vb[3]);
                    mma16816(o[1][2 * nn],     a1, vb[0], vb[1]);
                    mma16816(o[1][2 * nn + 1], a1, vb[2], vb[3]);
                }
            }
        }
    };

    for (int t = 0; t < NTH; t += 2) {
        if (t + 2 < NTH) { load_tile(t + 2); }
        CPA_COMMIT();
        do_tile(t);
        if (t + 3 < NTH) { load_tile(t + 3); }
        CPA_COMMIT();
        do_tile(t + 1);
        CPA_WAIT0();
        __syncthreads();
    }

    // ---- role decision: first finisher stores partial; later combines ----
    __syncthreads();
    if (tid == 0) s_pos = atomicAdd(&g_flag[job], 1);
    __syncthreads();

    float* Po = g_Po + (size_t)job * BQ * HD;
    float* Pl = g_Pl + (size_t)job * BQ;

    if (s_pos == 0) {
        // FIRST finisher: publish partial, signal ready, exit.
        #pragma unroll
        for (int rt = 0; rt < 2; rt++) {
            const int rr0 = w * 32 + rt * 16 + (lane >> 2);
            const int rr1 = rr0 + 8;
            if ((lane & 3) == 0) {
                Pl[rr0] = ol[rt][0];
                Pl[rr1] = ol[rt][2];
            }
            #pragma unroll
            for (int j = 0; j < 8; j++) {
                int col = j * 8 + (lane & 3) * 2;
                *reinterpret_cast<float2*>(Po + (size_t)rr0 * HD + col) =
                    make_float2(o[rt][j][0], o[rt][j][1]);
                *reinterpret_cast<float2*>(Po + (size_t)rr1 * HD + col) =
                    make_float2(o[rt][j][2], o[rt][j][3]);
            }
        }
        __threadfence();
        __syncthreads();                  // all partial writes fenced
        if (tid == 0) atomicExch(&g_ready[job], 1);
        return;
    }

    // LATER finisher: peer is resident and will set ready; spin briefly.
    if (tid == 0) {
        while (atomicAdd(&g_ready[job], 0) == 0) { }
    }
    __syncthreads();
    __threadfence();                      // acquire peer's partial

    float* Ob = O + (size_t)b * SEQ * HD;
    #pragma unroll
    for (int rt = 0; rt < 2; rt++) {
        const int rr0 = w * 32 + rt * 16 + (lane >> 2);
        const int rr1 = rr0 + 8;
        const int r0 = q0 + rr0;
        const int r1 = q0 + rr1;
        const float inv0 = 1.0f / (ol[rt][0] + Pl[rr0]);
        const float inv1 = 1.0f / (ol[rt][2] + Pl[rr1]);
        #pragma unroll
        for (int j = 0; j < 8; j++) {
            int col = j * 8 + (lane & 3) * 2;
            float2 e0 = *reinterpret_cast<const float2*>(Po + (size_t)rr0 * HD + col);
            float2 e1 = *reinterpret_cast<const float2*>(Po + (size_t)rr1 * HD + col);
            *reinterpret_cast<float2*>(Ob + (size_t)r0 * HD + col) =
                make_float2((o[rt][j][0] + e0.x) * inv0, (o[rt][j][1] + e0.y) * inv0);
            *reinterpret_cast<float2*>(Ob + (size_t)r1 * HD + col) =
                make_float2((o[rt][j][2] + e1.x) * inv1, (o[rt][j][3] + e1.y) * inv1);
        }
    }
    __syncthreads();
    if (tid == 0) {                        // reset for next graph replay
        g_flag[job]  = 0;
        g_ready[job] = 0;
    }
}

extern "C" void kernel_launch(void* const* d_in, const int* in_sizes, int n_in,
                              void* d_out, int out_size)
{
    (void)in_sizes; (void)n_in; (void)out_size;
    const float* Q = (const float*)d_in[0];
    const float* K = (const float*)d_in[1];
    const float* V = (const float*)d_in[2];
    float* O = (float*)d_out;

    prep<<<2048, 256>>>((const float4*)Q, (const float4*)K, (const float4*)V);

    dim3 grid(SEQ / BQ, BATCH, KSPLIT);   // (32, 16, 2) = 1024 half-jobs
    attn_hmma13<<<grid, THREADS>>>(O);
}

// round 16
// speedup vs baseline: 1.0271x; 1.0036x over previous
#include <cuda_runtime.h>
#include <cuda_fp16.h>
#include <cstdint>

// ============================================================
// Flash attention B=16 S=4096 D=64, fp32 in/out, HMMA path.
// Round 16: round-15 kernel (wait-free fused split-K=2, fp16x2
// exp2 softmax, ones-MMA row sums, 4-stage cp.async pipeline).
// Change: Q conversion fused into the main kernel (each CTA's
// Q block is private): load fp32 Q, scale+convert in regs,
// store swizzled fp16 to smem. prep handles only K and V ->
// prep traffic drops 75MB -> 50MB.
// ============================================================

#define BATCH 16
#define SEQ   4096
#define HD    64
#define BQ    128
#define BK    64
#define KSPLIT 2
#define SHALF (SEQ / KSPLIT)   // 2048
#define NTH   (SHALF / BK)     // 32 tiles per half-job
#define THREADS 128
#define NJOBS (BATCH * (SEQ / BQ))     // 512
#define QSCALE 0.18033688011112042f   // log2(e)/sqrt(64)
#define ONES2  0x3C003C00u             // __half2(1,1)

__device__ __half g_Kh[BATCH * SEQ * HD];
__device__ __half g_Vh[BATCH * SEQ * HD];
__device__ float  g_Po[NJOBS * BQ * HD];   // one partial per job (first finisher)
__device__ float  g_Pl[NJOBS * BQ];        // row sums of that partial
__device__ int    g_flag[NJOBS];           // arrival counter (zero-init)
__device__ int    g_ready[NJOBS];          // partial-visible flag (zero-init)

static __device__ __forceinline__ uint32_t smem_u32(const void* p) {
    uint32_t a;
    asm("{ .reg .u64 t; cvta.to.shared.u64 t, %1; cvt.u32.u64 %0, t; }"
        : "=r"(a) : "l"(p));
    return a;
}
static __device__ __forceinline__ void ldm_x4(uint32_t r[4], uint32_t addr) {
    asm volatile("ldmatrix.sync.aligned.m8n8.x4.shared.b16 {%0,%1,%2,%3}, [%4];"
                 : "=r"(r[0]), "=r"(r[1]), "=r"(r[2]), "=r"(r[3])
                 : "r"(addr) : "memory");
}
static __device__ __forceinline__ void ldm_x4_t(uint32_t r[4], uint32_t addr) {
    asm volatile("ldmatrix.sync.aligned.m8n8.x4.trans.shared.b16 {%0,%1,%2,%3}, [%4];"
                 : "=r"(r[0]), "=r"(r[1]), "=r"(r[2]), "=r"(r[3])
                 : "r"(addr) : "memory");
}
static __device__ __forceinline__ void mma16816(float (&c)[4], const uint32_t (&a)[4],
                                                uint32_t b0, uint32_t b1) {
    asm volatile("mma.sync.aligned.m16n8k16.row.col.f32.f16.f16.f32 "
                 "{%0,%1,%2,%3}, {%4,%5,%6,%7}, {%8,%9}, {%0,%1,%2,%3};"
                 : "+f"(c[0]), "+f"(c[1]), "+f"(c[2]), "+f"(c[3])
                 : "r"(a[0]), "r"(a[1]), "r"(a[2]), "r"(a[3]), "r"(b0), "r"(b1));
}
static __device__ __forceinline__ void cpa16(uint32_t dst, const void* src) {
    asm volatile("cp.async.cg.shared.global [%0], [%1], 16;"
                 :: "r"(dst), "l"(src) : "memory");
}
#define CPA_COMMIT() asm volatile("cp.async.commit_group;" ::: "memory")
#define CPA_WAIT0()  asm volatile("cp.async.wait_group 0;" ::: "memory")

static __device__ __forceinline__ uint32_t h2u(__half2 h) {
    return *reinterpret_cast<uint32_t*>(&h);
}
static __device__ __forceinline__ uint32_t swz(uint32_t off) {
    return off ^ ((off >> 3) & 0x70);
}
// pack two fp32 scores -> fp16x2, exp2 both halves in one MUFU op (no shift)
static __device__ __forceinline__ uint32_t p16x2(float a, float b) {
    __half2 h = __floats2half2_rn(a, b);
    uint32_t r;
    asm("ex2.approx.f16x2 %0, %1;" : "=r"(r) : "r"(h2u(h)));
    return r;
}

// ---------------- prep: K,V fp32 -> fp16 scratch (2 float4 / thread) ----------------
__global__ __launch_bounds__(256)
void prep(const float4* __restrict__ K4, const float4* __restrict__ V4)
{
    int i0 = blockIdx.x * 512 + threadIdx.x;
    int i1 = i0 + 256;
    float4 ka = K4[i0], kb = K4[i1];
    float4 va = V4[i0], vb = V4[i1];
    reinterpret_cast<uint2*>(g_Kh)[i0] = make_uint2(
        h2u(__floats2half2_rn(ka.x, ka.y)), h2u(__floats2half2_rn(ka.z, ka.w)));
    reinterpret_cast<uint2*>(g_Kh)[i1] = make_uint2(
        h2u(__floats2half2_rn(kb.x, kb.y)), h2u(__floats2half2_rn(kb.z, kb.w)));
    reinterpret_cast<uint2*>(g_Vh)[i0] = make_uint2(
        h2u(__floats2half2_rn(va.x, va.y)), h2u(__floats2half2_rn(va.z, va.w)));
    reinterpret_cast<uint2*>(g_Vh)[i1] = make_uint2(
        h2u(__floats2half2_rn(vb.x, vb.y)), h2u(__floats2half2_rn(vb.z, vb.w)));
}

// ---------------- main attention kernel (one K-half) ----------------
// smem: 4 x 16KB stages; in each: K tile +0 (8KB), V tile +8192 (8KB).
__global__ __launch_bounds__(THREADS, 3)
void attn_hmma14(const float4* __restrict__ Qg, float* __restrict__ O)
{
    __shared__ __align__(1024) char sm[65536];
    __shared__ int s_pos;
    const uint32_t smb = smem_u32(sm);
    const int tid  = threadIdx.x;
    const int lane = tid & 31;
    const int w    = tid >> 5;            // 0..3, warp owns 32 query rows
    const int b    = blockIdx.y;
    const int q0   = blockIdx.x * BQ;
    const int z    = blockIdx.z;          // K half
    const int job  = b * (SEQ / BQ) + blockIdx.x;

    const __half* Kb = g_Kh + ((size_t)b * SEQ + (size_t)z * SHALF) * HD;
    const __half* Vb = g_Vh + ((size_t)b * SEQ + (size_t)z * SHALF) * HD;

    // ---- fused Q stage: load fp32, scale+convert, store swizzled fp16 ----
    {
        const float4* Qblk = Qg + ((size_t)b * SEQ + q0) * (HD / 4);
        #pragma unroll
        for (int j = 0; j < 16; j++) {
            int idx = tid + j * THREADS;             // 0..2047 float4s
            float4 f = Qblk[idx];
            uint2 hv = make_uint2(
                h2u(__floats2half2_rn(f.x * QSCALE, f.y * QSCALE)),
                h2u(__floats2half2_rn(f.z * QSCALE, f.w * QSCALE)));
            uint32_t off = swz((uint32_t)(idx >> 4) * 128 + (uint32_t)(idx & 15) * 8);
            *reinterpret_cast<uint2*>(sm + off) = hv;
        }
    }
    __syncthreads();

    uint32_t q[2][4][4];
    {
        uint32_t colb = (uint32_t)(lane >> 4) * 16;
        #pragma unroll
        for (int rt = 0; rt < 2; rt++) {
            uint32_t row = (uint32_t)w * 32 + (uint32_t)rt * 16 + (lane & 15);
            #pragma unroll
            for (int c = 0; c < 4; c++) {
                uint32_t off = swz(row * 128 + (uint32_t)c * 32 + colb);
                ldm_x4(q[rt][c], smb + off);
            }
        }
    }
    __syncthreads();   // Q staging now reusable as stage 0

    auto load_tile = [&](int t) {
        uint32_t nb = smb + (uint32_t)(t & 3) * 16384u;
        const __half* kn = Kb + (size_t)t * BK * HD;
        const __half* vn = Vb + (size_t)t * BK * HD;
        #pragma unroll
        for (int j = 0; j < 4; j++) {
            int idx = tid + j * THREADS;             // 0..511
            uint32_t off = swz((uint32_t)(idx >> 3) * 128 + (uint32_t)(idx & 7) * 16);
            cpa16(nb + off,        kn + idx * 8);
            cpa16(nb + 8192 + off, vn + idx * 8);
        }
    };

    load_tile(0); CPA_COMMIT();
    load_tile(1); CPA_COMMIT();
    CPA_WAIT0();
    __syncthreads();

    float o[2][8][4];
    #pragma unroll
    for (int rt = 0; rt < 2; rt++)
        #pragma unroll
        for (int j = 0; j < 8; j++)
            o[rt][j][0] = o[rt][j][1] = o[rt][j][2] = o[rt][j][3] = 0.f;
    float ol[2][4];
    ol[0][0] = ol[0][1] = ol[0][2] = ol[0][3] = 0.f;
    ol[1][0] = ol[1][1] = ol[1][2] = ol[1][3] = 0.f;

    const uint32_t krow  = (uint32_t)(lane & 15);
    const uint32_t kcolb = (uint32_t)(lane >> 4) * 16;

    auto do_tile = [&](int t) {
        const uint32_t base = smb + (uint32_t)(t & 3) * 16384u;
        #pragma unroll
        for (int h = 0; h < 2; h++) {
            float s[2][4][4];
            #pragma unroll
            for (int rt = 0; rt < 2; rt++)
                #pragma unroll
                for (int j = 0; j < 4; j++)
                    s[rt][j][0] = s[rt][j][1] = s[rt][j][2] = s[rt][j][3] = 0.f;

            #pragma unroll
            for (int g = 0; g < 2; g++) {
                uint32_t kg = (uint32_t)(h * 2 + g);
                #pragma unroll
                for (int c = 0; c < 4; c++) {
                    uint32_t off = swz((kg * 16 + krow) * 128 + (uint32_t)c * 32 + kcolb);
                    uint32_t kb[4];
                    ldm_x4(kb, base + off);
                    #pragma unroll
                    for (int rt = 0; rt < 2; rt++) {
                        mma16816(s[rt][2 * g],     q[rt][c], kb[0], kb[2]);
                        mma16816(s[rt][2 * g + 1], q[rt][c], kb[1], kb[3]);
                    }
                }
            }

            uint32_t pu[2][4][2];
            #pragma unroll
            for (int rt = 0; rt < 2; rt++)
                #pragma unroll
                for (int j = 0; j < 4; j++) {
                    pu[rt][j][0] = p16x2(s[rt][j][0], s[rt][j][1]);
                    pu[rt][j][1] = p16x2(s[rt][j][2], s[rt][j][3]);
                }

            #pragma unroll
            for (int kk = 0; kk < 2; kk++) {
                uint32_t kg = (uint32_t)(h * 2 + kk);
                uint32_t a0[4] = { pu[0][2 * kk][0], pu[0][2 * kk][1],
                                   pu[0][2 * kk + 1][0], pu[0][2 * kk + 1][1] };
                uint32_t a1[4] = { pu[1][2 * kk][0], pu[1][2 * kk][1],
                                   pu[1][2 * kk + 1][0], pu[1][2 * kk + 1][1] };
                mma16816(ol[0], a0, ONES2, ONES2);
                mma16816(ol[1], a1, ONES2, ONES2);
                #pragma unroll
                for (int nn = 0; nn < 4; nn++) {
                    uint32_t off = swz((kg * 16 + krow) * 128 + (uint32_t)nn * 32 + kcolb);
                    uint32_t vb[4];
                    ldm_x4_t(vb, base + 8192 + off);
                    mma16816(o[0][2 * nn],     a0, vb[0], vb[1]);
                    mma16816(o[0][2 * nn + 1], a0, vb[2], vb[3]);
                    mma16816(o[1][2 * nn],     a1, vb[0], vb[1]);
                    mma16816(o[1][2 * nn + 1], a1, vb[2], vb[3]);
                }
            }
        }
    };

    for (int t = 0; t < NTH; t += 2) {
        if (t + 2 < NTH) { load_tile(t + 2); }
        CPA_COMMIT();
        do_tile(t);
        if (t + 3 < NTH) { load_tile(t + 3); }
        CPA_COMMIT();
        do_tile(t + 1);
        CPA_WAIT0();
        __syncthreads();
    }

    // ---- role decision: first finisher stores partial; later combines ----
    __syncthreads();
    if (tid == 0) s_pos = atomicAdd(&g_flag[job], 1);
    __syncthreads();

    float* Po = g_Po + (size_t)job * BQ * HD;
    float* Pl = g_Pl + (size_t)job * BQ;

    if (s_pos == 0) {
        // FIRST finisher: publish partial, signal ready, exit.
        #pragma unroll
        for (int rt = 0; rt < 2; rt++) {
            const int rr0 = w * 32 + rt * 16 + (lane >> 2);
            const int rr1 = rr0 + 8;
            if ((lane & 3) == 0) {
                Pl[rr0] = ol[rt][0];
                Pl[rr1] = ol[rt][2];
            }
            #pragma unroll
            for (int j = 0; j < 8; j++) {
                int col = j * 8 + (lane & 3) * 2;
                *reinterpret_cast<float2*>(Po + (size_t)rr0 * HD + col) =
                    make_float2(o[rt][j][0], o[rt][j][1]);
                *reinterpret_cast<float2*>(Po + (size_t)rr1 * HD + col) =
                    make_float2(o[rt][j][2], o[rt][j][3]);
            }
        }
        __threadfence();
        __syncthreads();                  // all partial writes fenced
        if (tid == 0) atomicExch(&g_ready[job], 1);
        return;
    }

    // LATER finisher: peer is resident and will set ready; spin briefly.
    if (tid == 0) {
        while (atomicAdd(&g_ready[job], 0) == 0) { }
    }
    __syncthreads();
    __threadfence();                      // acquire peer's partial

    float* Ob = O + (size_t)b * SEQ * HD;
    #pragma unroll
    for (int rt = 0; rt < 2; rt++) {
        const int rr0 = w * 32 + rt * 16 + (lane >> 2);
        const int rr1 = rr0 + 8;
        const int r0 = q0 + rr0;
        const int r1 = q0 + rr1;
        const float inv0 = 1.0f / (ol[rt][0] + Pl[rr0]);
        const float inv1 = 1.0f / (ol[rt][2] + Pl[rr1]);
        #pragma unroll
        for (int j = 0; j < 8; j++) {
            int col = j * 8 + (lane & 3) * 2;
            float2 e0 = *reinterpret_cast<const float2*>(Po + (size_t)rr0 * HD + col);
            float2 e1 = *reinterpret_cast<const float2*>(Po + (size_t)rr1 * HD + col);
            *reinterpret_cast<float2*>(Ob + (size_t)r0 * HD + col) =
                make_float2((o[rt][j][0] + e0.x) * inv0, (o[rt][j][1] + e0.y) * inv0);
            *reinterpret_cast<float2*>(Ob + (size_t)r1 * HD + col) =
                make_float2((o[rt][j][2] + e1.x) * inv1, (o[rt][j][3] + e1.y) * inv1);
        }
    }
    __syncthreads();
    if (tid == 0) {                        // reset for next graph replay
        g_flag[job]  = 0;
        g_ready[job] = 0;
    }
}

extern "C" void kernel_launch(void* const* d_in, const int* in_sizes, int n_in,
                              void* d_out, int out_size)
{
    (void)in_sizes; (void)n_in; (void)out_size;
    const float* Q = (const float*)d_in[0];
    const float* K = (const float*)d_in[1];
    const float* V = (const float*)d_in[2];
    float* O = (float*)d_out;

    prep<<<2048, 256>>>((const float4*)K, (const float4*)V);

    dim3 grid(SEQ / BQ, BATCH, KSPLIT);   // (32, 16, 2) = 1024 half-jobs
    attn_hmma14<<<grid, THREADS>>>((const float4*)Q, O);
}